// round 8
// baseline (speedup 1.0000x reference)
#include <cuda_runtime.h>
#include <cstdint>

// CapsNet dynamic routing — tensor-core GEMMs via mma.sync m16n8k8 tf32,
// 2-term hi/lo split (hi*hi + hi*lo + lo*hi), fp32 accumulation.
// R7: static __shared__ everywhere (48KB exact), no static guards, no host
// attribute calls — kernel_launch is stateless and graph-capturable.
// x: [256, 2401, 8] fp32   W: [2401, 8, 16, 8] fp32   out: [256, 8, 16] fp32

#define IN_CAPS 2401
#define BATCH 256
#define KTOT 19208
#define KPADS 19216      // 1201 * 16 (gemm_S k padding)
#define NROWS 19328      // 302 * 64  (gemm_Ya row padding)
#define NOC 128
#define NSPLIT 74

__device__ __align__(16) float g_Xp[(size_t)BATCH * KPADS];
__device__ __align__(16) float g_XT[(size_t)NROWS * BATCH];
__device__ __align__(16) float g_Vt[NOC * BATCH];
__device__ float g_Spart[(size_t)NSPLIT * BATCH * NOC];
__device__ float g_b[IN_CAPS * 8];
__device__ float g_C[IN_CAPS * 8];

// ---------------------------------------------------------------------------
__device__ __forceinline__ unsigned tf32_rna(float x) {
    unsigned r;
    asm("cvt.rna.tf32.f32 %0, %1;" : "=r"(r) : "f"(x));
    return r;
}
__device__ __forceinline__ void mma8(float* d, const unsigned* a, unsigned b0, unsigned b1) {
    asm volatile(
        "mma.sync.aligned.m16n8k8.row.col.f32.tf32.tf32.f32 "
        "{%0,%1,%2,%3}, {%4,%5,%6,%7}, {%8,%9}, {%0,%1,%2,%3};"
        : "+f"(d[0]), "+f"(d[1]), "+f"(d[2]), "+f"(d[3])
        : "r"(a[0]), "r"(a[1]), "r"(a[2]), "r"(a[3]), "r"(b0), "r"(b1));
}

// One 16-k slab of warp-level MMAs. Xs/Bs row stride 20 floats.
// Warp computes m16 (rows wm*16..) x n64 (cols wn*64..), acc[8][4].
__device__ __forceinline__ void slab_mma(const float* Xs, const float* Bs,
                                         float acc[8][4], int wm, int wn, int g, int tig) {
#pragma unroll
    for (int s = 0; s < 2; s++) {
        int kb = s * 8;
        float x0 = Xs[(wm * 16 + g) * 20 + kb + tig];
        float x1 = Xs[(wm * 16 + g + 8) * 20 + kb + tig];
        float x2 = Xs[(wm * 16 + g) * 20 + kb + tig + 4];
        float x3 = Xs[(wm * 16 + g + 8) * 20 + kb + tig + 4];
        unsigned ah[4] = {tf32_rna(x0), tf32_rna(x1), tf32_rna(x2), tf32_rna(x3)};
        unsigned al[4] = {__float_as_uint(x0 - __uint_as_float(ah[0])),
                          __float_as_uint(x1 - __uint_as_float(ah[1])),
                          __float_as_uint(x2 - __uint_as_float(ah[2])),
                          __float_as_uint(x3 - __uint_as_float(ah[3]))};
#pragma unroll
        for (int j = 0; j < 8; j++) {
            float b0f = Bs[(wn * 64 + j * 8 + g) * 20 + kb + tig];
            float b1f = Bs[(wn * 64 + j * 8 + g) * 20 + kb + tig + 4];
            unsigned bh0 = tf32_rna(b0f), bh1 = tf32_rna(b1f);
            unsigned bl0 = __float_as_uint(b0f - __uint_as_float(bh0));
            unsigned bl1 = __float_as_uint(b1f - __uint_as_float(bh1));
            mma8(acc[j], ah, bh0, bh1);
            mma8(acc[j], ah, bl0, bl1);
            mma8(acc[j], al, bh0, bh1);
        }
    }
}

// ---------------------------------------------------------------------------
__global__ void init_kernel() {
    int t = blockIdx.x * blockDim.x + threadIdx.x;
    if (t < IN_CAPS * 8) { g_b[t] = 0.0f; g_C[t] = 0.125f; }
}

// Pad/copy X -> g_Xp and transpose -> g_XT. grid (604, 8) x 256.
__global__ void __launch_bounds__(256) setup_kernel(const float* __restrict__ X) {
    __shared__ float s[32][33];
    int k0 = blockIdx.x * 32, b0 = blockIdx.y * 32;
    int tx = threadIdx.x & 31, ty = threadIdx.x >> 5;
#pragma unroll
    for (int j = 0; j < 4; j++) {
        int b = b0 + ty + j * 8;
        int k = k0 + tx;
        float v = (k < KTOT) ? X[(size_t)b * KTOT + k] : 0.0f;
        s[ty + j * 8][tx] = v;
        if (k < KPADS) g_Xp[(size_t)b * KPADS + k] = v;
    }
    __syncthreads();
#pragma unroll
    for (int j = 0; j < 4; j++) {
        int r = k0 + ty + j * 8;   // < 19328 always
        int b = b0 + tx;
        g_XT[(size_t)r * BATCH + b] = s[tx][ty + j * 8];
    }
}

// softmax over o for each capsule
__global__ void __launch_bounds__(128) compute_C_kernel() {
    int i = blockIdx.x * 128 + threadIdx.x;
    if (i >= IN_CAPS) return;
    float bv[8];
    float mx = -1e30f;
#pragma unroll
    for (int o = 0; o < 8; o++) { bv[o] = g_b[i * 8 + o]; mx = fmaxf(mx, bv[o]); }
    float sum = 0.0f;
#pragma unroll
    for (int o = 0; o < 8; o++) { bv[o] = expf(bv[o] - mx); sum += bv[o]; }
    float inv = 1.0f / sum;
#pragma unroll
    for (int o = 0; o < 8; o++) g_C[i * 8 + o] = bv[o] * inv;
}

// ---------------------------------------------------------------------------
// S = X @ (C.*W)^T, split-K partials. grid (4, 74) x 256 thr.
// CTA tile 64 batch x 128 n. B built on the fly from W and C.
__global__ void __launch_bounds__(256) gemm_S_kernel(const float* __restrict__ W) {
    __shared__ __align__(16) float Xs[64 * 20];
    __shared__ __align__(16) float Bs[128 * 20];

    int t = threadIdx.x;
    int w = t >> 5, lane = t & 31;
    int wm = w & 3, wn = w >> 2;
    int g = lane >> 2, tig = lane & 3;
    int b0 = blockIdx.x * 64;
    int split = blockIdx.y;
    int cbase = split * 16 + min(split, 17);
    int cnt = 16 + (split < 17 ? 1 : 0);

    float acc[8][4];
#pragma unroll
    for (int j = 0; j < 8; j++)
#pragma unroll
        for (int e = 0; e < 4; e++) acc[j][e] = 0.0f;

    int xrow = t >> 2, xk4 = t & 3;           // X: 1 float4 per thread
    float4 pxv, pbv[2];
    float pcc[2];

    {   // prefetch slab 0
        int k0 = cbase * 16;
        pxv = *reinterpret_cast<const float4*>(g_Xp + (size_t)(b0 + xrow) * KPADS + k0 + xk4 * 4);
#pragma unroll
        for (int p = 0; p < 2; p++) {
            int u = t + p * 256;
            int n = u >> 2, kk4 = u & 3;
            int i = (k0 >> 3) + (kk4 >> 1);
            int o = n >> 4, c = n & 15, d4 = (kk4 & 1) * 4;
            int iw = min(i, IN_CAPS - 1);
            pbv[p] = *reinterpret_cast<const float4*>(W + (size_t)iw * 1024 + o * 128 + c * 8 + d4);
            pcc[p] = (i < IN_CAPS) ? g_C[i * 8 + o] : 0.0f;
        }
    }

    for (int cs = 0; cs < cnt; cs++) {
        __syncthreads();
        *reinterpret_cast<float4*>(Xs + xrow * 20 + xk4 * 4) = pxv;
#pragma unroll
        for (int p = 0; p < 2; p++) {
            int u = t + p * 256;
            int n = u >> 2, kk4 = u & 3;
            float4 v = pbv[p];
            float cc = pcc[p];
            *reinterpret_cast<float4*>(Bs + n * 20 + kk4 * 4) =
                make_float4(cc * v.x, cc * v.y, cc * v.z, cc * v.w);
        }
        __syncthreads();

        if (cs + 1 < cnt) {
            int k0 = (cbase + cs + 1) * 16;
            pxv = *reinterpret_cast<const float4*>(g_Xp + (size_t)(b0 + xrow) * KPADS + k0 + xk4 * 4);
#pragma unroll
            for (int p = 0; p < 2; p++) {
                int u = t + p * 256;
                int n = u >> 2, kk4 = u & 3;
                int i = (k0 >> 3) + (kk4 >> 1);
                int o = n >> 4, c = n & 15, d4 = (kk4 & 1) * 4;
                int iw = min(i, IN_CAPS - 1);
                pbv[p] = *reinterpret_cast<const float4*>(W + (size_t)iw * 1024 + o * 128 + c * 8 + d4);
                pcc[p] = (i < IN_CAPS) ? g_C[i * 8 + o] : 0.0f;
            }
        }
        slab_mma(Xs, Bs, acc, wm, wn, g, tig);
    }

    float* dst = g_Spart + ((size_t)split * BATCH + b0 + wm * 16) * NOC + wn * 64;
#pragma unroll
    for (int j = 0; j < 8; j++) {
        int col = j * 8 + 2 * tig;
        *reinterpret_cast<float2*>(dst + g * NOC + col) = make_float2(acc[j][0], acc[j][1]);
        *reinterpret_cast<float2*>(dst + (g + 8) * NOC + col) = make_float2(acc[j][2], acc[j][3]);
    }
}

// ---------------------------------------------------------------------------
// Sum 74 partials + squash; writes g_Vt (fp32 transposed) or final out.
__global__ void __launch_bounds__(256) reduce_squash_kernel(float* __restrict__ out, int last) {
    int id = blockIdx.x * 256 + threadIdx.x;
    int gg = id >> 2;
    int q = id & 3;
    const float4* sp = reinterpret_cast<const float4*>(g_Spart);

    float4 s = make_float4(0.f, 0.f, 0.f, 0.f);
    for (int p = q; p < NSPLIT; p += 4) {
        float4 v = sp[(size_t)p * (BATCH * NOC / 4) + gg];
        s.x += v.x; s.y += v.y; s.z += v.z; s.w += v.w;
    }
#pragma unroll
    for (int off = 1; off <= 2; off <<= 1) {
        s.x += __shfl_xor_sync(0xffffffffu, s.x, off);
        s.y += __shfl_xor_sync(0xffffffffu, s.y, off);
        s.z += __shfl_xor_sync(0xffffffffu, s.z, off);
        s.w += __shfl_xor_sync(0xffffffffu, s.w, off);
    }
    float msq = s.x * s.x + s.y * s.y + s.z * s.z + s.w * s.w;
    msq += __shfl_xor_sync(0xffffffffu, msq, 4);
    msq += __shfl_xor_sync(0xffffffffu, msq, 8);
    float f = sqrtf(msq) / (1.0f + msq);
    float4 v = make_float4(s.x * f, s.y * f, s.z * f, s.w * f);
    if (q == 0) {
        if (last) {
            reinterpret_cast<float4*>(out)[gg] = v;
        } else {
            float vv[4] = {v.x, v.y, v.z, v.w};
            int b = gg >> 5, n0 = (gg & 31) * 4;
#pragma unroll
            for (int e = 0; e < 4; e++)
                g_Vt[(n0 + e) * BATCH + b] = vv[e];
        }
    }
}

// ---------------------------------------------------------------------------
// Y = XT @ Vt^T (K=256) + agreement epilogue -> g_b. grid 302 x 256 thr.
// CTA tile 64 rows (8 capsules) x 128 cols. Static smem = 48KB exactly.
__global__ void __launch_bounds__(256) gemm_Ya_kernel(const float* __restrict__ W) {
    __shared__ __align__(16) float Xs[64 * 20];      //  5120 B
    __shared__ __align__(16) float Bs[128 * 20];     // 10240 B
    __shared__ __align__(16) float Ysh[64 * 132];    // 33792 B  (total 49152)

    int t = threadIdx.x;
    int w = t >> 5, lane = t & 31;
    int wm = w & 3, wn = w >> 2;
    int g = lane >> 2, tig = lane & 3;
    int r0 = blockIdx.x * 64;

    float acc[8][4];
#pragma unroll
    for (int j = 0; j < 8; j++)
#pragma unroll
        for (int e = 0; e < 4; e++) acc[j][e] = 0.0f;

    int xrow = t >> 2, xk4 = t & 3;
    float4 pxv, pbv[2];
    pxv = *reinterpret_cast<const float4*>(g_XT + (size_t)(r0 + xrow) * BATCH + xk4 * 4);
#pragma unroll
    for (int p = 0; p < 2; p++) {
        int u = t + p * 256;
        int n = u >> 2, kk4 = u & 3;
        pbv[p] = *reinterpret_cast<const float4*>(g_Vt + n * BATCH + kk4 * 4);
    }

    for (int cs = 0; cs < 16; cs++) {
        __syncthreads();
        *reinterpret_cast<float4*>(Xs + xrow * 20 + xk4 * 4) = pxv;
#pragma unroll
        for (int p = 0; p < 2; p++) {
            int u = t + p * 256;
            int n = u >> 2, kk4 = u & 3;
            *reinterpret_cast<float4*>(Bs + n * 20 + kk4 * 4) = pbv[p];
        }
        __syncthreads();

        if (cs + 1 < 16) {
            int k0 = (cs + 1) * 16;
            pxv = *reinterpret_cast<const float4*>(g_XT + (size_t)(r0 + xrow) * BATCH + k0 + xk4 * 4);
#pragma unroll
            for (int p = 0; p < 2; p++) {
                int u = t + p * 256;
                int n = u >> 2, kk4 = u & 3;
                pbv[p] = *reinterpret_cast<const float4*>(g_Vt + n * BATCH + k0 + kk4 * 4);
            }
        }
        slab_mma(Xs, Bs, acc, wm, wn, g, tig);
    }

    // Stage Y tile, then agreement reduction.
#pragma unroll
    for (int j = 0; j < 8; j++) {
        int col = wn * 64 + j * 8 + 2 * tig;
        int row = wm * 16 + g;
        *reinterpret_cast<float2*>(&Ysh[row * 132 + col]) = make_float2(acc[j][0], acc[j][1]);
        *reinterpret_cast<float2*>(&Ysh[(row + 8) * 132 + col]) = make_float2(acc[j][2], acc[j][3]);
    }
    __syncthreads();

    // a[i,o] = (1/B) sum_{c,d} W[i,o,c,d] * Y[(i,d),(o,c)] ; b += a
    if (t < 64) {
        int il = t >> 3;
        int o = t & 7;
        int i = r0 / 8 + il;
        if (i < IN_CAPS) {
            const float4* w4 = reinterpret_cast<const float4*>(W + (size_t)i * 1024 + o * 128);
            float sum = 0.0f;
#pragma unroll
            for (int c = 0; c < 16; c++) {
                float4 wa = w4[c * 2];
                float4 wb = w4[c * 2 + 1];
                int col = o * 16 + c;
                int rb = il * 8;
                sum += wa.x * Ysh[(rb + 0) * 132 + col] + wa.y * Ysh[(rb + 1) * 132 + col] +
                       wa.z * Ysh[(rb + 2) * 132 + col] + wa.w * Ysh[(rb + 3) * 132 + col] +
                       wb.x * Ysh[(rb + 4) * 132 + col] + wb.y * Ysh[(rb + 5) * 132 + col] +
                       wb.z * Ysh[(rb + 6) * 132 + col] + wb.w * Ysh[(rb + 7) * 132 + col];
            }
            g_b[i * 8 + o] += sum * (1.0f / 256.0f);
        }
    }
}

// ---------------------------------------------------------------------------
extern "C" void kernel_launch(void* const* d_in, const int* in_sizes, int n_in,
                              void* d_out, int out_size) {
    const float* x;
    const float* W;
    if (in_sizes[0] == BATCH * KTOT) {
        x = (const float*)d_in[0];
        W = (const float*)d_in[1];
    } else {
        x = (const float*)d_in[1];
        W = (const float*)d_in[0];
    }
    float* out = (float*)d_out;

    init_kernel<<<76, 256>>>();
    setup_kernel<<<dim3(604, 8), 256>>>(x);

    for (int it = 0; it < 3; it++) {
        gemm_S_kernel<<<dim3(4, NSPLIT), 256>>>(W);
        reduce_squash_kernel<<<128, 256>>>(out, it == 2 ? 1 : 0);
        if (it < 2) {
            gemm_Ya_kernel<<<302, 256>>>(W);
            compute_C_kernel<<<19, 128>>>();
        }
    }
}